// round 3
// baseline (speedup 1.0000x reference)
#include <cuda_runtime.h>
#include <cstdint>

#define NC    192
#define HW    56
#define PLANE (HW*HW)
#define HALO  62
#define KK    49

typedef unsigned long long u64;

__device__ __forceinline__ u64 pack2(float lo, float hi) {
    return (u64)__float_as_uint(lo) | ((u64)__float_as_uint(hi) << 32);
}

__device__ __forceinline__ u64 ffma2(u64 a, u64 b, u64 c) {
    u64 d;
    asm("fma.rn.f32x2 %0, %1, %2, %3;" : "=l"(d) : "l"(a), "l"(b), "l"(c));
    return d;
}

// mantissa_map: a = |v|+1e-7 (always normal); m = mantissa(a) in [1,2);
// M = m>=1.5 ? m/2 : m   (== reference's piecewise map, in [0.75,1.5))
__device__ __forceinline__ float mant_map(float v) {
    float a = fabsf(v) + 1e-7f;
    unsigned u = __float_as_uint(a);
    float m = __uint_as_float((u & 0x007FFFFFu) | 0x3F800000u);
    return (m >= 1.5f) ? m * 0.5f : m;
}

__global__ void __launch_bounds__(256)
appro_waconv_kernel(const float* __restrict__ x,
                    const float* __restrict__ w,
                    float* __restrict__ out)
{
    __shared__ u64 sh[HALO * HALO];   // (x, x/M1) packed, zero halo
    __shared__ u64 shw[KK];           // (A, w-A) packed

    const int plane = blockIdx.x;          // b*NC + c
    const int c = plane % NC;
    const float* __restrict__ xin = x + (size_t)plane * PLANE;

    const int tx  = threadIdx.x;           // 0..63
    const int tid = threadIdx.y * 64 + tx; // 0..255

    // --- weights: A = w/M2, B = w - A (49 taps, this channel) ---
    if (tid < KK) {
        float wv = w[c * KK + tid];
        float M2 = mant_map(wv);
        float A  = wv / M2;
        shw[tid] = pack2(A, wv - A);
    }

    // --- input halo tile: packed (x, x/M1); zeros in the 3-wide pad ---
    for (int cell = tid; cell < HALO * HALO; cell += 256) {
        int hy = cell / HALO;
        int hx = cell - hy * HALO;
        int iy = hy - 3, ix = hx - 3;
        u64 v = 0ull;
        if ((unsigned)iy < (unsigned)HW && (unsigned)ix < (unsigned)HW) {
            float xv = __ldg(&xin[iy * HW + ix]);
            float M1 = mant_map(xv);
            float xr = __fdividef(xv, M1);
            v = pack2(xv, xr);
        }
        sh[cell] = v;
    }
    __syncthreads();

    if (tx >= HW) return;   // lanes 56..63 only help load (no further barriers)

    // weights into registers (broadcast LDS, one-time)
    u64 wr[KK];
#pragma unroll
    for (int i = 0; i < KK; ++i) wr[i] = shw[i];

    const int oy0 = threadIdx.y * 14;      // 4 * 14 = 56 rows
    u64 acc[14];
#pragma unroll
    for (int i = 0; i < 14; ++i) acc[i] = 0ull;

    const u64* __restrict__ row0 = &sh[oy0 * HALO + tx];

    // sliding-row reuse: 20 input rows feed 14 output rows
#pragma unroll
    for (int r = 0; r < 20; ++r) {
        u64 p[7];
#pragma unroll
        for (int j = 0; j < 7; ++j) p[j] = row0[r * HALO + j];
#pragma unroll
        for (int k = 0; k < 7; ++k) {
            const int i = r - k;
            if (i >= 0 && i < 14) {
#pragma unroll
                for (int j = 0; j < 7; ++j)
                    acc[i] = ffma2(p[j], wr[k * 7 + j], acc[i]);
            }
        }
    }

    float* __restrict__ o = out + (size_t)plane * PLANE + oy0 * HW + tx;
#pragma unroll
    for (int i = 0; i < 14; ++i) {
        float lo = __uint_as_float((unsigned)(acc[i] & 0xFFFFFFFFull));
        float hi = __uint_as_float((unsigned)(acc[i] >> 32));
        o[i * HW] = lo + hi;
    }
}

extern "C" void kernel_launch(void* const* d_in, const int* in_sizes, int n_in,
                              void* d_out, int out_size)
{
    const float* x = (const float*)d_in[0];      // (4,192,56,56) fp32
    const float* w = (const float*)d_in[1];      // (192,1,7,7)   fp32
    float* out = (float*)d_out;                  // (4,192,56,56) fp32

    dim3 block(64, 4);
    dim3 grid(4 * NC);                           // one block per (b,c) plane
    appro_waconv_kernel<<<grid, block>>>(x, w, out);
}